// round 1
// baseline (speedup 1.0000x reference)
#include <cuda_runtime.h>
#include <cstdint>

#define FULL 0xffffffffu

// Problem dims
constexpr int Bb = 512;
constexpr int Vv = 64;
constexpr int Dd = 32;
constexpr int Hh = 64;
constexpr int Aa = 8;
constexpr int Ee = Vv * (Vv - 1);   // 4032

// Output layout: [tanh_mu B*V*A][logp B*V][aug B*V*96]
constexpr size_t OUT_TANH = 0;
constexpr size_t OUT_LOGP = (size_t)Bb * Vv * Aa;          // 262144
constexpr size_t OUT_AUG  = OUT_LOGP + (size_t)Bb * Vv;    // 294912

__device__ __forceinline__ float relu(float x) { return fmaxf(x, 0.0f); }

constexpr float HALF_LOG_2PI_F = 0.91893853320467274f;
constexpr float LOG2_F         = 0.69314718055994531f;

// ============================================================================
// Kernel 1: fused edge MLP + aggregation.
// Grid (8, B). Block 256 = 8 warps. Warp w handles receiver r = bx*8 + w for
// batch b = by. Each warp iterates over the 63 incoming edges (senders) in
// blocks of 4, keeping the running agg sum in registers (no atomics).
// Writes aug = [inputs[b,r,:] | agg[b,r,:]] directly into d_out.
// ============================================================================
__global__ __launch_bounds__(256) void edge_kernel(
    const float* __restrict__ inputs,   // [B,V,D]
    const float* __restrict__ edges,    // [B,E,2]
    const float* __restrict__ m1w,      // [2D,H]
    const float* __restrict__ m1b,      // [H]
    const float* __restrict__ m2w,      // [H,H]
    const float* __restrict__ m2b,      // [H]
    float* __restrict__ out)
{
    __shared__ float2 sw1[64][32];   // sw1[k][l] = (m1w[k][l], m1w[k][l+32])
    __shared__ float2 sw2[64][32];
    __shared__ float  sx[64][32];    // inputs[b]
    __shared__ float  sb1[64];
    __shared__ float  sb2[64];

    const int b   = blockIdx.y;
    const int tid = threadIdx.x;

    for (int i = tid; i < 64 * 32; i += 256) {
        int k = i >> 5, l = i & 31;
        sw1[k][l] = make_float2(m1w[k * 64 + l], m1w[k * 64 + l + 32]);
        sw2[k][l] = make_float2(m2w[k * 64 + l], m2w[k * 64 + l + 32]);
        sx[k][l]  = inputs[(size_t)b * (Vv * Dd) + i];
    }
    if (tid < 64) { sb1[tid] = m1b[tid]; sb2[tid] = m2b[tid]; }
    __syncthreads();

    const int lane = tid & 31;
    const int w    = tid >> 5;
    const int r    = blockIdx.x * 8 + w;

    // h_base: bias + recv-half of MLP1 (shared by all 63 edges of this r)
    float hb0 = sb1[lane], hb1 = sb1[lane + 32];
    #pragma unroll
    for (int k = 0; k < 32; k++) {
        float p = sx[r][k];
        float2 wv = sw1[k][lane];
        hb0 = fmaf(p, wv.x, hb0);
        hb1 = fmaf(p, wv.y, hb1);
    }

    float acc0 = 0.f, acc1 = 0.f;   // agg[r][lane], agg[r][lane+32]

    for (int ib = 0; ib < 16; ib++) {
        float xs[4], ew[4];
        #pragma unroll
        for (int j = 0; j < 4; j++) {
            int idx = ib * 4 + j;          // 0..63 (63 = dummy, ew=0)
            bool valid = (idx < 63);
            int s = valid ? (idx + (idx >= r ? 1 : 0)) : r;
            int e = valid ? (s * 63 + (r < s ? r : r - 1)) : 0;
            ew[j] = valid ? edges[((size_t)b * Ee + e) * 2 + 1] : 0.0f;
            xs[j] = sx[s][lane];
        }

        float h0[4], h1[4];
        #pragma unroll
        for (int j = 0; j < 4; j++) { h0[j] = hb0; h1[j] = hb1; }

        // send-half of MLP1
        #pragma unroll
        for (int k = 0; k < 32; k++) {
            float2 wv = sw1[32 + k][lane];
            #pragma unroll
            for (int j = 0; j < 4; j++) {
                float p = __shfl_sync(FULL, xs[j], k);
                h0[j] = fmaf(p, wv.x, h0[j]);
                h1[j] = fmaf(p, wv.y, h1[j]);
            }
        }
        #pragma unroll
        for (int j = 0; j < 4; j++) { h0[j] = relu(h0[j]); h1[j] = relu(h1[j]); }

        // MLP2
        float m0[4], m1[4];
        #pragma unroll
        for (int j = 0; j < 4; j++) { m0[j] = sb2[lane]; m1[j] = sb2[lane + 32]; }
        #pragma unroll
        for (int k = 0; k < 32; k++) {
            float2 wv = sw2[k][lane];
            #pragma unroll
            for (int j = 0; j < 4; j++) {
                float p = __shfl_sync(FULL, h0[j], k);
                m0[j] = fmaf(p, wv.x, m0[j]);
                m1[j] = fmaf(p, wv.y, m1[j]);
            }
        }
        #pragma unroll
        for (int k = 0; k < 32; k++) {
            float2 wv = sw2[32 + k][lane];
            #pragma unroll
            for (int j = 0; j < 4; j++) {
                float p = __shfl_sync(FULL, h1[j], k);
                m0[j] = fmaf(p, wv.x, m0[j]);
                m1[j] = fmaf(p, wv.y, m1[j]);
            }
        }
        #pragma unroll
        for (int j = 0; j < 4; j++) {
            acc0 = fmaf(relu(m0[j]), ew[j], acc0);
            acc1 = fmaf(relu(m1[j]), ew[j], acc1);
        }
    }

    float* aug = out + OUT_AUG + ((size_t)b * Vv + r) * 96;
    aug[lane]      = sx[r][lane];
    aug[32 + lane] = acc0;
    aug[64 + lane] = acc1;
}

// ============================================================================
// Kernel 2: node MLP head. Warp-per-row over B*V = 32768 rows.
// Reads aug from d_out, writes tanh(mu) and logp.
// ============================================================================
__global__ __launch_bounds__(256) void node_kernel(
    const float* __restrict__ fc1w,  // [96,64]
    const float* __restrict__ fc1b,
    const float* __restrict__ fc2w,  // [64,64]
    const float* __restrict__ fc2b,
    const float* __restrict__ muw,   // [64,8]
    const float* __restrict__ mub,
    const float* __restrict__ lsw,   // [64,8]
    const float* __restrict__ lsb,
    float* __restrict__ out)
{
    __shared__ float2 s1[96][32];
    __shared__ float2 s2[64][32];
    __shared__ float  smu[8][64];   // transposed: smu[a][k]
    __shared__ float  sls[8][64];
    __shared__ float  sb1[64], sb2[64], sbm[8], sbl[8];

    const int tid = threadIdx.x;
    for (int i = tid; i < 96 * 32; i += 256) {
        int k = i >> 5, l = i & 31;
        s1[k][l] = make_float2(fc1w[k * 64 + l], fc1w[k * 64 + l + 32]);
    }
    for (int i = tid; i < 64 * 32; i += 256) {
        int k = i >> 5, l = i & 31;
        s2[k][l] = make_float2(fc2w[k * 64 + l], fc2w[k * 64 + l + 32]);
    }
    for (int i = tid; i < 64 * 8; i += 256) {
        int k = i >> 3, a = i & 7;    // row-major [64][8]
        smu[a][k] = muw[i];
        sls[a][k] = lsw[i];
    }
    if (tid < 64) { sb1[tid] = fc1b[tid]; sb2[tid] = fc2b[tid]; }
    if (tid < 8)  { sbm[tid] = mub[tid];  sbl[tid] = lsb[tid]; }
    __syncthreads();

    const int lane = tid & 31;
    const int w    = tid >> 5;

    for (int i = 0; i < 8; i++) {
        int row = blockIdx.x * 64 + i * 8 + w;     // 512 blocks * 64 rows
        const float* arow = out + OUT_AUG + (size_t)row * 96;
        float a0 = arow[lane], a1 = arow[32 + lane], a2 = arow[64 + lane];

        // fc1: [96] -> [64]
        float g0 = sb1[lane], g1 = sb1[lane + 32];
        #pragma unroll
        for (int k = 0; k < 32; k++) {
            float p = __shfl_sync(FULL, a0, k);
            float2 wv = s1[k][lane];
            g0 = fmaf(p, wv.x, g0); g1 = fmaf(p, wv.y, g1);
        }
        #pragma unroll
        for (int k = 0; k < 32; k++) {
            float p = __shfl_sync(FULL, a1, k);
            float2 wv = s1[32 + k][lane];
            g0 = fmaf(p, wv.x, g0); g1 = fmaf(p, wv.y, g1);
        }
        #pragma unroll
        for (int k = 0; k < 32; k++) {
            float p = __shfl_sync(FULL, a2, k);
            float2 wv = s1[64 + k][lane];
            g0 = fmaf(p, wv.x, g0); g1 = fmaf(p, wv.y, g1);
        }
        g0 = relu(g0); g1 = relu(g1);

        // fc2: [64] -> [64]
        float t0 = sb2[lane], t1 = sb2[lane + 32];
        #pragma unroll
        for (int k = 0; k < 32; k++) {
            float p = __shfl_sync(FULL, g0, k);
            float2 wv = s2[k][lane];
            t0 = fmaf(p, wv.x, t0); t1 = fmaf(p, wv.y, t1);
        }
        #pragma unroll
        for (int k = 0; k < 32; k++) {
            float p = __shfl_sync(FULL, g1, k);
            float2 wv = s2[32 + k][lane];
            t0 = fmaf(p, wv.x, t0); t1 = fmaf(p, wv.y, t1);
        }
        t0 = relu(t0); t1 = relu(t1);

        // heads: mu, log_std, tanh, logp
        float logp = 0.f, mytanh = 0.f;
        #pragma unroll
        for (int a = 0; a < Aa; a++) {
            float pm = t0 * smu[a][lane] + t1 * smu[a][lane + 32];
            float pl = t0 * sls[a][lane] + t1 * sls[a][lane + 32];
            #pragma unroll
            for (int off = 16; off; off >>= 1) {
                pm += __shfl_xor_sync(FULL, pm, off);
                pl += __shfl_xor_sync(FULL, pl, off);
            }
            float mu = pm + sbm[a];
            float ls = fminf(fmaxf(pl + sbl[a], -3.0f), 1.0f);
            // softplus(-2mu), numerically stable
            float x  = -2.0f * mu;
            float sp = fmaxf(x, 0.0f) + log1pf(expf(-fabsf(x)));
            logp += -ls - HALF_LOG_2PI_F - 2.0f * (LOG2_F - mu - sp);
            if (lane == a) mytanh = tanhf(mu);
        }
        if (lane < Aa) out[OUT_TANH + (size_t)row * Aa + lane] = mytanh;
        if (lane == 0) out[OUT_LOGP + row] = logp;
    }
}

extern "C" void kernel_launch(void* const* d_in, const int* in_sizes, int n_in,
                              void* d_out, int out_size) {
    (void)in_sizes; (void)n_in; (void)out_size;
    const float* inputs = (const float*)d_in[0];
    const float* edges  = (const float*)d_in[1];
    const float* m1w    = (const float*)d_in[2];
    const float* m1b    = (const float*)d_in[3];
    const float* m2w    = (const float*)d_in[4];
    const float* m2b    = (const float*)d_in[5];
    const float* fc1w   = (const float*)d_in[6];
    const float* fc1b   = (const float*)d_in[7];
    const float* fc2w   = (const float*)d_in[8];
    const float* fc2b   = (const float*)d_in[9];
    const float* muw    = (const float*)d_in[10];
    const float* mub    = (const float*)d_in[11];
    const float* lsw    = (const float*)d_in[12];
    const float* lsb    = (const float*)d_in[13];
    // d_in[14]=send_e, d_in[15]=recv_e: edge order is the deterministic
    // row-major np.where(ones-eye) enumeration, recomputed analytically.
    float* out = (float*)d_out;

    edge_kernel<<<dim3(8, Bb), 256>>>(inputs, edges, m1w, m1b, m2w, m2b, out);
    node_kernel<<<512, 256>>>(fc1w, fc1b, fc2w, fc2b, muw, mub, lsw, lsb, out);
}

// round 2
// speedup vs baseline: 2.1313x; 2.1313x over previous
#include <cuda_runtime.h>
#include <cstdint>

#define FULL 0xffffffffu
typedef unsigned long long ull;

// Problem dims
constexpr int Bb = 512;
constexpr int Vv = 64;
constexpr int Dd = 32;
constexpr int Aa = 8;
constexpr int Ee = Vv * (Vv - 1);   // 4032

// Output layout: [tanh_mu B*V*A][logp B*V][aug B*V*96]
constexpr size_t OUT_TANH = 0;
constexpr size_t OUT_LOGP = (size_t)Bb * Vv * Aa;          // 262144
constexpr size_t OUT_AUG  = OUT_LOGP + (size_t)Bb * Vv;    // 294912

__device__ __forceinline__ float relu(float x) { return fmaxf(x, 0.0f); }

constexpr float HALF_LOG_2PI_F = 0.91893853320467274f;
constexpr float LOG2_F         = 0.69314718055994531f;

// ---- packed fp32x2 helpers (sm_103a) ----
__device__ __forceinline__ ull fma2(ull a, ull b, ull c) {
    ull d;
    asm("fma.rn.f32x2 %0, %1, %2, %3;" : "=l"(d) : "l"(a), "l"(b), "l"(c));
    return d;
}
__device__ __forceinline__ ull packdup(float x) {
    ull d;
    asm("mov.b64 %0, {%1, %1};" : "=l"(d) : "f"(x));
    return d;
}
__device__ __forceinline__ ull pack2(float lo, float hi) {
    ull d;
    asm("mov.b64 %0, {%1, %2};" : "=l"(d) : "f"(lo), "f"(hi));
    return d;
}

// ============================================================================
// Edge kernel V2.
// Grid (8, B), block 256 = 8 warps; warp w handles receiver r = bx*8 + w.
//
// Factorization: h[e] = relu(hb[r] + hs[s]) where
//   hb[v][c] = b1[c] + sum_{k<32} x[v][k] * m1w[k][c]        (recv half)
//   hs[v][c] =          sum_{k<32} x[v][k] * m1w[32+k][c]    (send half)
// Both precomputed per block. Per edge only MLP2 remains (64x64), done with
// packed fp32x2 FMA, h broadcast from smem (no shuffles), agg in registers.
// ============================================================================
struct EdgeSmem {
    float  shs [64][68];     // hs, padded rows (68 floats = 272B)
    float  shb [8][68];      // hb for this block's 8 receivers
    float  hbuf[8][8][68];   // per-warp 8-edge h tile
    float2 sxd [64][32];     // inputs duplicated pairs (x,x)
    float2 sw2p[64][32];     // m2w packed: (w[k][c], w[k][c+32])
    float  sew [8][64];      // edge weights per warp
    float2 sb2p[32];         // m2b packed
};

__global__ __launch_bounds__(256) void edge_kernel(
    const float* __restrict__ inputs,   // [B,V,D]
    const float* __restrict__ edges,    // [B,E,2]
    const float* __restrict__ m1w,      // [2D,H]
    const float* __restrict__ m1b,      // [H]
    const float* __restrict__ m2w,      // [H,H]
    const float* __restrict__ m2b,      // [H]
    float* __restrict__ out)
{
    extern __shared__ char smem_raw[];
    EdgeSmem* sm = reinterpret_cast<EdgeSmem*>(smem_raw);

    const int b    = blockIdx.y;
    const int tid  = threadIdx.x;
    const int lane = tid & 31;
    const int w    = tid >> 5;
    const int r    = blockIdx.x * 8 + w;

    // ---- prologue: stage x (duplicated), w2 (packed), b2 (packed) ----
    for (int i = tid; i < 64 * 32; i += 256) {
        int v = i >> 5, k = i & 31;
        float x = inputs[(size_t)b * (Vv * Dd) + i];
        sm->sxd[v][k] = make_float2(x, x);
        int kk = i >> 5, c = i & 31;
        sm->sw2p[kk][c] = make_float2(m2w[kk * 64 + c], m2w[kk * 64 + c + 32]);
    }
    if (tid < 32) sm->sb2p[tid] = make_float2(m2b[tid], m2b[tid + 32]);
    __syncthreads();

    // ---- hs for nodes v = w*8 .. w*8+7 (send-half weights m1w[32..63]) ----
    {
        ull w1s[32];
        #pragma unroll
        for (int k = 0; k < 32; k++)
            w1s[k] = pack2(m1w[(32 + k) * 64 + lane], m1w[(32 + k) * 64 + lane + 32]);
        #pragma unroll
        for (int vi = 0; vi < 8; vi++) {
            int v = w * 8 + vi;
            ull acc = 0ull;
            #pragma unroll
            for (int k = 0; k < 32; k++) {
                ull xv = *reinterpret_cast<const ull*>(&sm->sxd[v][k]);
                acc = fma2(xv, w1s[k], acc);
            }
            float2 h2 = *reinterpret_cast<float2*>(&acc);
            sm->shs[v][lane]      = h2.x;
            sm->shs[v][lane + 32] = h2.y;
        }
    }
    // ---- hb for this warp's receiver r (recv-half weights m1w[0..31] + bias) ----
    {
        ull w1r[32];
        #pragma unroll
        for (int k = 0; k < 32; k++)
            w1r[k] = pack2(m1w[k * 64 + lane], m1w[k * 64 + lane + 32]);
        ull accb = pack2(m1b[lane], m1b[lane + 32]);
        #pragma unroll
        for (int k = 0; k < 32; k++) {
            ull xv = *reinterpret_cast<const ull*>(&sm->sxd[r][k]);
            accb = fma2(xv, w1r[k], accb);
        }
        float2 h2 = *reinterpret_cast<float2*>(&accb);
        sm->shb[w][lane]      = h2.x;
        sm->shb[w][lane + 32] = h2.y;
    }
    // ---- edge weights for this receiver (63 valid + 1 dummy) ----
    for (int t = lane; t < 64; t += 32) {
        float ewv = 0.0f;
        if (t < 63) {
            int s = t + (t >= r ? 1 : 0);
            int e = s * 63 + (r < s ? r : r - 1);
            ewv = edges[((size_t)b * Ee + e) * 2 + 1];
        }
        sm->sew[w][t] = ewv;
    }
    __syncthreads();

    // ---- main loop: 8 chunks of 8 edges ----
    const ull b2pk = *reinterpret_cast<const ull*>(&sm->sb2p[lane]);
    float acc0 = 0.f, acc1 = 0.f;

    const int ep = lane & 7;   // edge within chunk (phase 1 role)
    const int kg = lane >> 3;  // k-group 0..3 (16 k's each)

    for (int chunk = 0; chunk < 8; chunk++) {
        // phase 1: build h tile for 8 edges (lane = edge x kgroup)
        {
            int idx = chunk * 8 + ep;
            int s = (idx < 63) ? (idx + (idx >= r ? 1 : 0)) : r;
            const float* hsrow = &sm->shs[s][0];
            const float* hbrow = &sm->shb[w][0];
            float* hdst = &sm->hbuf[w][ep][0];
            #pragma unroll
            for (int j = 0; j < 4; j++) {
                int k = kg * 16 + j * 4;
                float4 a4 = *reinterpret_cast<const float4*>(hsrow + k);
                float4 c4 = *reinterpret_cast<const float4*>(hbrow + k);
                float4 h4;
                h4.x = relu(a4.x + c4.x);
                h4.y = relu(a4.y + c4.y);
                h4.z = relu(a4.z + c4.z);
                h4.w = relu(a4.w + c4.w);
                *reinterpret_cast<float4*>(hdst + k) = h4;
            }
        }
        __syncwarp();

        // phase 2: MLP2 for 8 edges, lane = channel pair (c, c+32)
        ull macc[8];
        #pragma unroll
        for (int e2 = 0; e2 < 8; e2++) macc[e2] = b2pk;

        #pragma unroll
        for (int k4 = 0; k4 < 16; k4++) {
            ull wp0 = *reinterpret_cast<const ull*>(&sm->sw2p[k4 * 4 + 0][lane]);
            ull wp1 = *reinterpret_cast<const ull*>(&sm->sw2p[k4 * 4 + 1][lane]);
            ull wp2 = *reinterpret_cast<const ull*>(&sm->sw2p[k4 * 4 + 2][lane]);
            ull wp3 = *reinterpret_cast<const ull*>(&sm->sw2p[k4 * 4 + 3][lane]);
            #pragma unroll
            for (int e2 = 0; e2 < 8; e2++) {
                float4 h4 = *reinterpret_cast<const float4*>(&sm->hbuf[w][e2][k4 * 4]);
                macc[e2] = fma2(packdup(h4.x), wp0, macc[e2]);
                macc[e2] = fma2(packdup(h4.y), wp1, macc[e2]);
                macc[e2] = fma2(packdup(h4.z), wp2, macc[e2]);
                macc[e2] = fma2(packdup(h4.w), wp3, macc[e2]);
            }
        }
        #pragma unroll
        for (int e2 = 0; e2 < 8; e2++) {
            float2 m = *reinterpret_cast<float2*>(&macc[e2]);
            float ew = sm->sew[w][chunk * 8 + e2];
            acc0 = fmaf(relu(m.x), ew, acc0);
            acc1 = fmaf(relu(m.y), ew, acc1);
        }
        __syncwarp();
    }

    float* aug = out + OUT_AUG + ((size_t)b * Vv + r) * 96;
    aug[lane]      = sm->sxd[r][lane].x;
    aug[32 + lane] = acc0;
    aug[64 + lane] = acc1;
}

// ============================================================================
// Kernel 2: node MLP head (unchanged from R1).
// ============================================================================
__global__ __launch_bounds__(256) void node_kernel(
    const float* __restrict__ fc1w,  // [96,64]
    const float* __restrict__ fc1b,
    const float* __restrict__ fc2w,  // [64,64]
    const float* __restrict__ fc2b,
    const float* __restrict__ muw,   // [64,8]
    const float* __restrict__ mub,
    const float* __restrict__ lsw,   // [64,8]
    const float* __restrict__ lsb,
    float* __restrict__ out)
{
    __shared__ float2 s1[96][32];
    __shared__ float2 s2[64][32];
    __shared__ float  smu[8][64];
    __shared__ float  sls[8][64];
    __shared__ float  sb1[64], sb2[64], sbm[8], sbl[8];

    const int tid = threadIdx.x;
    for (int i = tid; i < 96 * 32; i += 256) {
        int k = i >> 5, l = i & 31;
        s1[k][l] = make_float2(fc1w[k * 64 + l], fc1w[k * 64 + l + 32]);
    }
    for (int i = tid; i < 64 * 32; i += 256) {
        int k = i >> 5, l = i & 31;
        s2[k][l] = make_float2(fc2w[k * 64 + l], fc2w[k * 64 + l + 32]);
    }
    for (int i = tid; i < 64 * 8; i += 256) {
        int k = i >> 3, a = i & 7;
        smu[a][k] = muw[i];
        sls[a][k] = lsw[i];
    }
    if (tid < 64) { sb1[tid] = fc1b[tid]; sb2[tid] = fc2b[tid]; }
    if (tid < 8)  { sbm[tid] = mub[tid];  sbl[tid] = lsb[tid]; }
    __syncthreads();

    const int lane = tid & 31;
    const int w    = tid >> 5;

    for (int i = 0; i < 8; i++) {
        int row = blockIdx.x * 64 + i * 8 + w;
        const float* arow = out + OUT_AUG + (size_t)row * 96;
        float a0 = arow[lane], a1 = arow[32 + lane], a2 = arow[64 + lane];

        float g0 = sb1[lane], g1 = sb1[lane + 32];
        #pragma unroll
        for (int k = 0; k < 32; k++) {
            float p = __shfl_sync(FULL, a0, k);
            float2 wv = s1[k][lane];
            g0 = fmaf(p, wv.x, g0); g1 = fmaf(p, wv.y, g1);
        }
        #pragma unroll
        for (int k = 0; k < 32; k++) {
            float p = __shfl_sync(FULL, a1, k);
            float2 wv = s1[32 + k][lane];
            g0 = fmaf(p, wv.x, g0); g1 = fmaf(p, wv.y, g1);
        }
        #pragma unroll
        for (int k = 0; k < 32; k++) {
            float p = __shfl_sync(FULL, a2, k);
            float2 wv = s1[64 + k][lane];
            g0 = fmaf(p, wv.x, g0); g1 = fmaf(p, wv.y, g1);
        }
        g0 = relu(g0); g1 = relu(g1);

        float t0 = sb2[lane], t1 = sb2[lane + 32];
        #pragma unroll
        for (int k = 0; k < 32; k++) {
            float p = __shfl_sync(FULL, g0, k);
            float2 wv = s2[k][lane];
            t0 = fmaf(p, wv.x, t0); t1 = fmaf(p, wv.y, t1);
        }
        #pragma unroll
        for (int k = 0; k < 32; k++) {
            float p = __shfl_sync(FULL, g1, k);
            float2 wv = s2[32 + k][lane];
            t0 = fmaf(p, wv.x, t0); t1 = fmaf(p, wv.y, t1);
        }
        t0 = relu(t0); t1 = relu(t1);

        float logp = 0.f, mytanh = 0.f;
        #pragma unroll
        for (int a = 0; a < Aa; a++) {
            float pm = t0 * smu[a][lane] + t1 * smu[a][lane + 32];
            float pl = t0 * sls[a][lane] + t1 * sls[a][lane + 32];
            #pragma unroll
            for (int off = 16; off; off >>= 1) {
                pm += __shfl_xor_sync(FULL, pm, off);
                pl += __shfl_xor_sync(FULL, pl, off);
            }
            float mu = pm + sbm[a];
            float ls = fminf(fmaxf(pl + sbl[a], -3.0f), 1.0f);
            float x  = -2.0f * mu;
            float sp = fmaxf(x, 0.0f) + log1pf(expf(-fabsf(x)));
            logp += -ls - HALF_LOG_2PI_F - 2.0f * (LOG2_F - mu - sp);
            if (lane == a) mytanh = tanhf(mu);
        }
        if (lane < Aa) out[OUT_TANH + (size_t)row * Aa + lane] = mytanh;
        if (lane == 0) out[OUT_LOGP + row] = logp;
    }
}

extern "C" void kernel_launch(void* const* d_in, const int* in_sizes, int n_in,
                              void* d_out, int out_size) {
    (void)in_sizes; (void)n_in; (void)out_size;
    const float* inputs = (const float*)d_in[0];
    const float* edges  = (const float*)d_in[1];
    const float* m1w    = (const float*)d_in[2];
    const float* m1b    = (const float*)d_in[3];
    const float* m2w    = (const float*)d_in[4];
    const float* m2b    = (const float*)d_in[5];
    const float* fc1w   = (const float*)d_in[6];
    const float* fc1b   = (const float*)d_in[7];
    const float* fc2w   = (const float*)d_in[8];
    const float* fc2b   = (const float*)d_in[9];
    const float* muw    = (const float*)d_in[10];
    const float* mub    = (const float*)d_in[11];
    const float* lsw    = (const float*)d_in[12];
    const float* lsb    = (const float*)d_in[13];
    float* out = (float*)d_out;

    cudaFuncSetAttribute(edge_kernel,
                         cudaFuncAttributeMaxDynamicSharedMemorySize,
                         (int)sizeof(EdgeSmem));
    edge_kernel<<<dim3(8, Bb), 256, sizeof(EdgeSmem)>>>(
        inputs, edges, m1w, m1b, m2w, m2b, out);
    node_kernel<<<512, 256>>>(fc1w, fc1b, fc2w, fc2b, muw, mub, lsw, lsb, out);
}

// round 3
// speedup vs baseline: 2.3588x; 1.1067x over previous
#include <cuda_runtime.h>
#include <cstdint>

#define FULL 0xffffffffu
typedef unsigned long long ull;
typedef ulonglong2 ull2;

// Problem dims
constexpr int Bb = 512;
constexpr int Vv = 64;
constexpr int Aa = 8;
constexpr int Ee = Vv * (Vv - 1);   // 4032

// Output layout: [tanh_mu B*V*A][logp B*V][aug B*V*96]
constexpr size_t OUT_TANH = 0;
constexpr size_t OUT_LOGP = (size_t)Bb * Vv * Aa;          // 262144
constexpr size_t OUT_AUG  = OUT_LOGP + (size_t)Bb * Vv;    // 294912

__device__ __forceinline__ float relu(float x) { return fmaxf(x, 0.0f); }

constexpr float HALF_LOG_2PI_F = 0.91893853320467274f;
constexpr float LOG2_F         = 0.69314718055994531f;

// ---- packed fp32x2 helpers (sm_103a) ----
__device__ __forceinline__ ull fma2(ull a, ull b, ull c) {
    ull d;
    asm("fma.rn.f32x2 %0, %1, %2, %3;" : "=l"(d) : "l"(a), "l"(b), "l"(c));
    return d;
}
__device__ __forceinline__ ull packdup(float x) {
    ull d;
    asm("mov.b64 %0, {%1, %1};" : "=l"(d) : "f"(x));
    return d;
}
__device__ __forceinline__ ull pack2(float lo, float hi) {
    ull d;
    asm("mov.b64 %0, {%1, %2};" : "=l"(d) : "f"(lo), "f"(hi));
    return d;
}

// Scratch for MLP1 halves: hb = bias + recv-half, hs = send-half.
__device__ float g_hb[(size_t)Bb * Vv * 64];
__device__ float g_hs[(size_t)Bb * Vv * 64];

// ============================================================================
// Kernel 0: MLP1 halves per (b,v). Warp per row, 8 warps/block, grid 4096.
// ============================================================================
__global__ __launch_bounds__(256) void mlp1_kernel(
    const float* __restrict__ inputs,   // [B*V, 32]
    const float* __restrict__ m1w,      // [64,64]
    const float* __restrict__ m1b)      // [64]
{
    __shared__ ull wr[32][32];   // recv-half weights packed (c, c+32)
    __shared__ ull ws[32][32];   // send-half
    __shared__ ull sbb[32];

    const int tid = threadIdx.x;
    for (int i = tid; i < 32 * 32; i += 256) {
        int k = i >> 5, c = i & 31;
        wr[k][c] = pack2(m1w[k * 64 + c],        m1w[k * 64 + c + 32]);
        ws[k][c] = pack2(m1w[(32 + k) * 64 + c], m1w[(32 + k) * 64 + c + 32]);
    }
    if (tid < 32) sbb[tid] = pack2(m1b[tid], m1b[tid + 32]);
    __syncthreads();

    const int lane = tid & 31;
    const int w    = tid >> 5;
    const size_t row = (size_t)blockIdx.x * 8 + w;

    float xval = inputs[row * 32 + lane];
    ull ab = sbb[lane];
    ull as2 = 0ull;
    #pragma unroll
    for (int k = 0; k < 32; k++) {
        ull p = packdup(__shfl_sync(FULL, xval, k));
        ab  = fma2(p, wr[k][lane], ab);
        as2 = fma2(p, ws[k][lane], as2);
    }
    float2 fb = *reinterpret_cast<float2*>(&ab);
    float2 fs = *reinterpret_cast<float2*>(&as2);
    g_hb[row * 64 + lane]      = fb.x;
    g_hb[row * 64 + lane + 32] = fb.y;
    g_hs[row * 64 + lane]      = fs.x;
    g_hs[row * 64 + lane + 32] = fs.y;
}

// ============================================================================
// Kernel 1: edge MLP2 + aggregation. Grid (8, B), block 256 = 8 warps;
// warp w handles receiver r = bx*8 + w.  h[e] = relu(hb[r] + hs[s]).
// MLP2 uses even/odd-K packed fp32x2: acc.lo/hi accumulate even/odd K terms.
// ============================================================================
struct EdgeSmem {
    float shs [64][68];      // hs for all 64 senders of this batch
    float shb [8][68];       // hb for this block's 8 receivers
    float hbuf[8][8][68];    // per-warp 8-edge h tile (plain floats)
    ull   sw2I[32][64];      // interleaved m2w: [kpair][c] = (w[2kp][c], w[2kp+1][c])
    float sew [8][64];       // edge weights per warp
    float sb2 [64];
};

__global__ __launch_bounds__(256) void edge_kernel(
    const float* __restrict__ inputs,   // [B,V,32]
    const float* __restrict__ edges,    // [B,E,2]
    const float* __restrict__ m2w,      // [64,64]
    const float* __restrict__ m2b,      // [64]
    float* __restrict__ out)
{
    extern __shared__ char smem_raw[];
    EdgeSmem* sm = reinterpret_cast<EdgeSmem*>(smem_raw);

    const int b    = blockIdx.y;
    const int tid  = threadIdx.x;
    const int lane = tid & 31;
    const int w    = tid >> 5;
    const int r    = blockIdx.x * 8 + w;

    // ---- prologue ----
    {
        const float* hs_g = g_hs + ((size_t)b * 64) * 64;
        for (int i = tid; i < 64 * 64; i += 256)
            sm->shs[i >> 6][i & 63] = hs_g[i];
        for (int i = tid; i < 8 * 64; i += 256) {
            int vr = blockIdx.x * 8 + (i >> 6);
            sm->shb[i >> 6][i & 63] = g_hb[((size_t)b * 64 + vr) * 64 + (i & 63)];
        }
        for (int i = tid; i < 32 * 64; i += 256) {
            int kp = i >> 6, c = i & 63;
            sm->sw2I[kp][c] = pack2(m2w[(2 * kp) * 64 + c], m2w[(2 * kp + 1) * 64 + c]);
        }
        if (tid < 64) sm->sb2[tid] = m2b[tid];
    }
    // edge weights for this receiver (63 valid + 1 dummy)
    for (int t = lane; t < 64; t += 32) {
        float ewv = 0.0f;
        if (t < 63) {
            int s = t + (t >= r ? 1 : 0);
            int e = s * 63 + (r < s ? r : r - 1);
            ewv = edges[((size_t)b * Ee + e) * 2 + 1];
        }
        sm->sew[w][t] = ewv;
    }
    __syncthreads();

    float acc0 = 0.f, acc1 = 0.f;   // agg[r][lane], agg[r][lane+32]
    const float bias0 = sm->sb2[lane];
    const float bias1 = sm->sb2[lane + 32];

    const int ep = lane & 7;   // edge within chunk (phase-1 role)
    const int kg = lane >> 3;  // k-group 0..3 (16 k's each)

    #pragma unroll 1
    for (int chunk = 0; chunk < 8; chunk++) {
        // phase 1: build h tile for 8 edges
        {
            int idx = chunk * 8 + ep;
            int s = (idx < 63) ? (idx + (idx >= r ? 1 : 0)) : r;
            const float* hsrow = &sm->shs[s][0];
            const float* hbrow = &sm->shb[w][0];
            float* hdst = &sm->hbuf[w][ep][0];
            #pragma unroll
            for (int j = 0; j < 4; j++) {
                int k = kg * 16 + j * 4;
                float4 a4 = *reinterpret_cast<const float4*>(hsrow + k);
                float4 c4 = *reinterpret_cast<const float4*>(hbrow + k);
                float4 h4;
                h4.x = relu(a4.x + c4.x);
                h4.y = relu(a4.y + c4.y);
                h4.z = relu(a4.z + c4.z);
                h4.w = relu(a4.w + c4.w);
                *reinterpret_cast<float4*>(hdst + k) = h4;
            }
        }
        __syncwarp();

        // phase 2: MLP2, even/odd-K packed. alo[e] = (ch=lane even-sum, odd-sum),
        // ahi[e] = same for ch=lane+32.
        ull alo[8], ahi[8];
        #pragma unroll
        for (int e = 0; e < 8; e++) { alo[e] = 0ull; ahi[e] = 0ull; }

        #pragma unroll 1
        for (int kp4 = 0; kp4 < 8; kp4++) {       // 4 k-pairs (8 k) per iter
            ull wl[4], wh[4];
            #pragma unroll
            for (int j = 0; j < 4; j++) {
                wl[j] = sm->sw2I[kp4 * 4 + j][lane];
                wh[j] = sm->sw2I[kp4 * 4 + j][lane + 32];
            }
            #pragma unroll
            for (int e = 0; e < 8; e++) {
                const ull2* hp = reinterpret_cast<const ull2*>(&sm->hbuf[w][e][kp4 * 8]);
                ull2 ha = hp[0];
                ull2 hb2 = hp[1];
                alo[e] = fma2(ha.x,  wl[0], alo[e]);  ahi[e] = fma2(ha.x,  wh[0], ahi[e]);
                alo[e] = fma2(ha.y,  wl[1], alo[e]);  ahi[e] = fma2(ha.y,  wh[1], ahi[e]);
                alo[e] = fma2(hb2.x, wl[2], alo[e]);  ahi[e] = fma2(hb2.x, wh[2], ahi[e]);
                alo[e] = fma2(hb2.y, wl[3], alo[e]);  ahi[e] = fma2(hb2.y, wh[3], ahi[e]);
            }
        }
        #pragma unroll
        for (int e = 0; e < 8; e++) {
            float2 pl = *reinterpret_cast<float2*>(&alo[e]);
            float2 ph = *reinterpret_cast<float2*>(&ahi[e]);
            float m0 = relu(pl.x + pl.y + bias0);
            float m1v = relu(ph.x + ph.y + bias1);
            float ew = sm->sew[w][chunk * 8 + e];
            acc0 = fmaf(m0, ew, acc0);
            acc1 = fmaf(m1v, ew, acc1);
        }
        __syncwarp();
    }

    float* aug = out + OUT_AUG + ((size_t)b * Vv + r) * 96;
    aug[lane]      = inputs[((size_t)b * 64 + r) * 32 + lane];
    aug[32 + lane] = acc0;
    aug[64 + lane] = acc1;
}

// ============================================================================
// Kernel 2: node MLP head. 8 warps/block, warp handles 8 rows; grid 512.
// fc1/fc2 use the same even/odd-K packed fp32x2 scheme; one reusable
// per-warp buffer holds aug -> g -> t. Seg-split head (no per-a shuffle loop).
// ============================================================================
struct NodeSmem {
    ull   s1I[48][64];      // fc1w interleaved [kpair][c]
    ull   s2I[32][64];      // fc2w interleaved
    float buf[8][8][104];   // per warp, per row: aug(96) -> g(64) -> t(64)
    float smu[8][64];       // muw transposed [a][k]
    float sls[8][64];
    float sb1[64], sb2[64], sbm[8], sbl[8];
};

__global__ __launch_bounds__(256) void node_kernel(
    const float* __restrict__ fc1w,  // [96,64]
    const float* __restrict__ fc1b,
    const float* __restrict__ fc2w,  // [64,64]
    const float* __restrict__ fc2b,
    const float* __restrict__ muw,   // [64,8]
    const float* __restrict__ mub,
    const float* __restrict__ lsw,   // [64,8]
    const float* __restrict__ lsb,
    float* __restrict__ out)
{
    extern __shared__ char smem_raw[];
    NodeSmem* sm = reinterpret_cast<NodeSmem*>(smem_raw);

    const int tid  = threadIdx.x;
    const int lane = tid & 31;
    const int w    = tid >> 5;

    for (int i = tid; i < 48 * 64; i += 256) {
        int kp = i >> 6, c = i & 63;
        sm->s1I[kp][c] = pack2(fc1w[(2 * kp) * 64 + c], fc1w[(2 * kp + 1) * 64 + c]);
    }
    for (int i = tid; i < 32 * 64; i += 256) {
        int kp = i >> 6, c = i & 63;
        sm->s2I[kp][c] = pack2(fc2w[(2 * kp) * 64 + c], fc2w[(2 * kp + 1) * 64 + c]);
    }
    for (int i = tid; i < 64 * 8; i += 256) {
        int k = i >> 3, a = i & 7;   // row-major [64][8]
        sm->smu[a][k] = muw[i];
        sm->sls[a][k] = lsw[i];
    }
    if (tid < 64) { sm->sb1[tid] = fc1b[tid]; sm->sb2[tid] = fc2b[tid]; }
    if (tid < 8)  { sm->sbm[tid] = mub[tid];  sm->sbl[tid] = lsb[tid]; }
    __syncthreads();

    const int rowbase = blockIdx.x * 64 + w * 8;

    // ---- stage aug rows (plain floats) ----
    if (lane < 24) {
        #pragma unroll
        for (int rr = 0; rr < 8; rr++) {
            const float4* src = reinterpret_cast<const float4*>(
                out + OUT_AUG + (size_t)(rowbase + rr) * 96);
            *reinterpret_cast<float4*>(&sm->buf[w][rr][lane * 4]) = src[lane];
        }
    }
    __syncwarp();

    // ---- fc1: 96 -> 64 ----
    ull alo[8], ahi[8];
    #pragma unroll
    for (int rr = 0; rr < 8; rr++) { alo[rr] = 0ull; ahi[rr] = 0ull; }
    #pragma unroll 1
    for (int kp4 = 0; kp4 < 12; kp4++) {
        ull wl[4], wh[4];
        #pragma unroll
        for (int j = 0; j < 4; j++) {
            wl[j] = sm->s1I[kp4 * 4 + j][lane];
            wh[j] = sm->s1I[kp4 * 4 + j][lane + 32];
        }
        #pragma unroll
        for (int rr = 0; rr < 8; rr++) {
            const ull2* hp = reinterpret_cast<const ull2*>(&sm->buf[w][rr][kp4 * 8]);
            ull2 ha = hp[0];
            ull2 hb2 = hp[1];
            alo[rr] = fma2(ha.x,  wl[0], alo[rr]);  ahi[rr] = fma2(ha.x,  wh[0], ahi[rr]);
            alo[rr] = fma2(ha.y,  wl[1], alo[rr]);  ahi[rr] = fma2(ha.y,  wh[1], ahi[rr]);
            alo[rr] = fma2(hb2.x, wl[2], alo[rr]);  ahi[rr] = fma2(hb2.x, wh[2], ahi[rr]);
            alo[rr] = fma2(hb2.y, wl[3], alo[rr]);  ahi[rr] = fma2(hb2.y, wh[3], ahi[rr]);
        }
    }
    __syncwarp();
    {
        const float b0 = sm->sb1[lane], b1 = sm->sb1[lane + 32];
        #pragma unroll
        for (int rr = 0; rr < 8; rr++) {
            float2 pl = *reinterpret_cast<float2*>(&alo[rr]);
            float2 ph = *reinterpret_cast<float2*>(&ahi[rr]);
            sm->buf[w][rr][lane]      = relu(pl.x + pl.y + b0);
            sm->buf[w][rr][lane + 32] = relu(ph.x + ph.y + b1);
        }
    }
    __syncwarp();

    // ---- fc2: 64 -> 64 ----
    #pragma unroll
    for (int rr = 0; rr < 8; rr++) { alo[rr] = 0ull; ahi[rr] = 0ull; }
    #pragma unroll 1
    for (int kp4 = 0; kp4 < 8; kp4++) {
        ull wl[4], wh[4];
        #pragma unroll
        for (int j = 0; j < 4; j++) {
            wl[j] = sm->s2I[kp4 * 4 + j][lane];
            wh[j] = sm->s2I[kp4 * 4 + j][lane + 32];
        }
        #pragma unroll
        for (int rr = 0; rr < 8; rr++) {
            const ull2* hp = reinterpret_cast<const ull2*>(&sm->buf[w][rr][kp4 * 8]);
            ull2 ha = hp[0];
            ull2 hb2 = hp[1];
            alo[rr] = fma2(ha.x,  wl[0], alo[rr]);  ahi[rr] = fma2(ha.x,  wh[0], ahi[rr]);
            alo[rr] = fma2(ha.y,  wl[1], alo[rr]);  ahi[rr] = fma2(ha.y,  wh[1], ahi[rr]);
            alo[rr] = fma2(hb2.x, wl[2], alo[rr]);  ahi[rr] = fma2(hb2.x, wh[2], ahi[rr]);
            alo[rr] = fma2(hb2.y, wl[3], alo[rr]);  ahi[rr] = fma2(hb2.y, wh[3], ahi[rr]);
        }
    }
    __syncwarp();
    {
        const float b0 = sm->sb2[lane], b1 = sm->sb2[lane + 32];
        #pragma unroll
        for (int rr = 0; rr < 8; rr++) {
            float2 pl = *reinterpret_cast<float2*>(&alo[rr]);
            float2 ph = *reinterpret_cast<float2*>(&ahi[rr]);
            sm->buf[w][rr][lane]      = relu(pl.x + pl.y + b0);
            sm->buf[w][rr][lane + 32] = relu(ph.x + ph.y + b1);
        }
    }
    __syncwarp();

    // ---- heads: seg-split. lane = a*4 + seg; seg covers 16 k's. ----
    const int a   = lane >> 2;
    const int seg = lane & 3;
    #pragma unroll 1
    for (int rr = 0; rr < 8; rr++) {
        const int row = rowbase + rr;
        const float* trow = &sm->buf[w][rr][0];
        float pm = 0.f, pl = 0.f;
        #pragma unroll
        for (int j4 = 0; j4 < 4; j4++) {
            int k = seg * 16 + j4 * 4;
            float4 tv = *reinterpret_cast<const float4*>(trow + k);
            float4 mv = *reinterpret_cast<const float4*>(&sm->smu[a][k]);
            float4 lv = *reinterpret_cast<const float4*>(&sm->sls[a][k]);
            pm = fmaf(tv.x, mv.x, pm); pm = fmaf(tv.y, mv.y, pm);
            pm = fmaf(tv.z, mv.z, pm); pm = fmaf(tv.w, mv.w, pm);
            pl = fmaf(tv.x, lv.x, pl); pl = fmaf(tv.y, lv.y, pl);
            pl = fmaf(tv.z, lv.z, pl); pl = fmaf(tv.w, lv.w, pl);
        }
        pm += __shfl_xor_sync(FULL, pm, 1); pm += __shfl_xor_sync(FULL, pm, 2);
        pl += __shfl_xor_sync(FULL, pl, 1); pl += __shfl_xor_sync(FULL, pl, 2);

        float mu = pm + sm->sbm[a];
        float ls = fminf(fmaxf(pl + sm->sbl[a], -3.0f), 1.0f);
        float x  = -2.0f * mu;
        float sp = fmaxf(x, 0.0f) + log1pf(expf(-fabsf(x)));
        float c  = -ls - HALF_LOG_2PI_F - 2.0f * (LOG2_F - mu - sp);

        if (seg == 0) out[OUT_TANH + (size_t)row * Aa + a] = tanhf(mu);

        float val = (seg == 0) ? c : 0.f;
        val += __shfl_xor_sync(FULL, val, 4);
        val += __shfl_xor_sync(FULL, val, 8);
        val += __shfl_xor_sync(FULL, val, 16);
        if (lane == 0) out[OUT_LOGP + row] = val;
    }
}

extern "C" void kernel_launch(void* const* d_in, const int* in_sizes, int n_in,
                              void* d_out, int out_size) {
    (void)in_sizes; (void)n_in; (void)out_size;
    const float* inputs = (const float*)d_in[0];
    const float* edges  = (const float*)d_in[1];
    const float* m1w    = (const float*)d_in[2];
    const float* m1b    = (const float*)d_in[3];
    const float* m2w    = (const float*)d_in[4];
    const float* m2b    = (const float*)d_in[5];
    const float* fc1w   = (const float*)d_in[6];
    const float* fc1b   = (const float*)d_in[7];
    const float* fc2w   = (const float*)d_in[8];
    const float* fc2b   = (const float*)d_in[9];
    const float* muw    = (const float*)d_in[10];
    const float* mub    = (const float*)d_in[11];
    const float* lsw    = (const float*)d_in[12];
    const float* lsb    = (const float*)d_in[13];
    float* out = (float*)d_out;

    cudaFuncSetAttribute(edge_kernel,
                         cudaFuncAttributeMaxDynamicSharedMemorySize,
                         (int)sizeof(EdgeSmem));
    cudaFuncSetAttribute(node_kernel,
                         cudaFuncAttributeMaxDynamicSharedMemorySize,
                         (int)sizeof(NodeSmem));

    mlp1_kernel<<<4096, 256>>>(inputs, m1w, m1b);
    edge_kernel<<<dim3(8, Bb), 256, sizeof(EdgeSmem)>>>(
        inputs, edges, m2w, m2b, out);
    node_kernel<<<512, 256, sizeof(NodeSmem)>>>(
        fc1w, fc1b, fc2w, fc2b, muw, mub, lsw, lsb, out);
}

// round 5
// speedup vs baseline: 5.5107x; 2.3362x over previous
#include <cuda_runtime.h>
#include <cstdint>

#define FULL 0xffffffffu
typedef unsigned long long ull;
typedef ulonglong2 ull2;

// Problem dims
constexpr int Bb = 512;
constexpr int Vv = 64;
constexpr int Aa = 8;
constexpr int Ee = Vv * (Vv - 1);   // 4032

// Output layout: [tanh_mu B*V*A][logp B*V][aug B*V*96]
constexpr size_t OUT_TANH = 0;
constexpr size_t OUT_LOGP = (size_t)Bb * Vv * Aa;          // 262144
constexpr size_t OUT_AUG  = OUT_LOGP + (size_t)Bb * Vv;    // 294912

__device__ __forceinline__ float relu(float x) { return fmaxf(x, 0.0f); }

constexpr float HALF_LOG_2PI_F = 0.91893853320467274f;
constexpr float LOG2_F         = 0.69314718055994531f;

// ---- packed fp32x2 helpers ----
__device__ __forceinline__ ull fma2(ull a, ull b, ull c) {
    ull d;
    asm("fma.rn.f32x2 %0, %1, %2, %3;" : "=l"(d) : "l"(a), "l"(b), "l"(c));
    return d;
}
__device__ __forceinline__ ull packdup(float x) {
    ull d;
    asm("mov.b64 %0, {%1, %1};" : "=l"(d) : "f"(x));
    return d;
}
__device__ __forceinline__ ull pack2(float lo, float hi) {
    ull d;
    asm("mov.b64 %0, {%1, %2};" : "=l"(d) : "f"(lo), "f"(hi));
    return d;
}
__device__ __forceinline__ uint32_t to_tf32(float x) {
    uint32_t r;
    asm("cvt.rna.tf32.f32 %0, %1;" : "=r"(r) : "f"(x));
    return r;
}

// m16n8k8 tf32 mma (legacy warp-level path, works on plain sm_103 target)
__device__ __forceinline__ void mma_tf32(float c[4], const uint32_t a[4],
                                         uint32_t b0, uint32_t b1) {
    asm volatile(
        "mma.sync.aligned.m16n8k8.row.col.f32.tf32.tf32.f32 "
        "{%0,%1,%2,%3}, {%4,%5,%6,%7}, {%8,%9}, {%0,%1,%2,%3};"
        : "+f"(c[0]), "+f"(c[1]), "+f"(c[2]), "+f"(c[3])
        : "r"(a[0]), "r"(a[1]), "r"(a[2]), "r"(a[3]), "r"(b0), "r"(b1));
}

// Scratch for MLP1 halves
__device__ float g_hb[(size_t)Bb * Vv * 64];
__device__ float g_hs[(size_t)Bb * Vv * 64];

// ============================================================================
// Kernel 0: MLP1 halves per (b,v); also copies inputs into aug[:, :, 0:32].
// ============================================================================
__global__ __launch_bounds__(256) void mlp1_kernel(
    const float* __restrict__ inputs,   // [B*V, 32]
    const float* __restrict__ m1w,      // [64,64]
    const float* __restrict__ m1b,      // [64]
    float* __restrict__ out)
{
    __shared__ ull wr[32][32];
    __shared__ ull ws[32][32];
    __shared__ ull sbb[32];

    const int tid = threadIdx.x;
    for (int i = tid; i < 32 * 32; i += 256) {
        int k = i >> 5, c = i & 31;
        wr[k][c] = pack2(m1w[k * 64 + c],        m1w[k * 64 + c + 32]);
        ws[k][c] = pack2(m1w[(32 + k) * 64 + c], m1w[(32 + k) * 64 + c + 32]);
    }
    if (tid < 32) sbb[tid] = pack2(m1b[tid], m1b[tid + 32]);
    __syncthreads();

    const int lane = tid & 31;
    const int w    = tid >> 5;
    const size_t row = (size_t)blockIdx.x * 8 + w;

    float xval = inputs[row * 32 + lane];
    ull ab = sbb[lane];
    ull as2 = 0ull;
    #pragma unroll
    for (int k = 0; k < 32; k++) {
        ull p = packdup(__shfl_sync(FULL, xval, k));
        ab  = fma2(p, wr[k][lane], ab);
        as2 = fma2(p, ws[k][lane], as2);
    }
    float2 fb = *reinterpret_cast<float2*>(&ab);
    float2 fs = *reinterpret_cast<float2*>(&as2);
    g_hb[row * 64 + lane]      = fb.x;
    g_hb[row * 64 + lane + 32] = fb.y;
    g_hs[row * 64 + lane]      = fs.x;
    g_hs[row * 64 + lane + 32] = fs.y;
    out[OUT_AUG + row * 96 + lane] = xval;   // aug[:, 0:32]
}

// ============================================================================
// Kernel 1: edge MLP2 via warp-level tf32 mma.sync + fp32 aggregation.
// Block = one batch, 8 warps; each warp handles 8 receivers.
// Per receiver: [64x64] A (h rows) x [64x64] m2w, M tiles of m16n8k8.
// ============================================================================
// dynamic smem layout (float indices)
constexpr int SHS   = 0;                 // hs [64][68] padded
constexpr int SHB   = SHS + 64 * 68;     // hb [64][64]
constexpr int SBF   = SHB + 64 * 64;     // B frags [8nt*8ks][64]
constexpr int SEW   = SBF + 64 * 64;     // ew [64][64]
constexpr int SBIAS = SEW + 64 * 64;     // [64]
constexpr int EDGE_SMEM_F = SBIAS + 64;  // total floats
constexpr int EDGE_SMEM_B = EDGE_SMEM_F * 4;

__global__ __launch_bounds__(256) void edge_kernel(
    const float* __restrict__ edges,    // [B,E,2]
    const float* __restrict__ m2w,      // [64,64]
    const float* __restrict__ m2b,      // [64]
    float* __restrict__ out)
{
    extern __shared__ float sf[];
    const int b    = blockIdx.x;
    const int tid  = threadIdx.x;
    const int lane = tid & 31;
    const int w    = tid >> 5;
    const int g    = lane >> 2;   // group id (rows / n-cols)
    const int tig  = lane & 3;    // thread in group (k / col pairs)

    // ---- prologue ----
    {
        const float* hs_g = g_hs + (size_t)b * 4096;
        const float* hb_g = g_hb + (size_t)b * 4096;
        for (int i = tid; i < 4096; i += 256) {
            sf[SHS + (i >> 6) * 68 + (i & 63)] = hs_g[i];
            sf[SHB + i] = hb_g[i];
        }
        // B fragments (fragment-major): frag = nt*8+ks, lane li holds
        // (m2w[ks*8+tig][nt*8+g], m2w[ks*8+tig+4][nt*8+g]) as tf32 bits.
        for (int i = tid; i < 4096; i += 256) {
            int frag = i >> 6;
            int li   = (i & 63) >> 1;
            int p    = i & 1;
            int nt = frag >> 3, ks = frag & 7;
            int gg = li >> 2, tt = li & 3;
            int k = ks * 8 + tt + 4 * p;
            int n = nt * 8 + gg;
            sf[SBF + frag * 64 + li * 2 + p] =
                __uint_as_float(to_tf32(m2w[k * 64 + n]));
        }
        // edge weights: linear over E, scatter to [recv][j]
        for (int i = tid; i < Ee; i += 256) {
            int s = i / 63, t = i % 63;
            int r = t + (t >= s ? 1 : 0);
            int j = s - (s > r ? 1 : 0);
            sf[SEW + r * 64 + j] = edges[((size_t)b * Ee + i) * 2 + 1];
        }
        if (tid < 64) {
            sf[SEW + tid * 64 + 63] = 0.0f;   // pad row weight
            sf[SBIAS + tid] = m2b[tid];
        }
    }
    __syncthreads();

    #pragma unroll 1
    for (int ri = 0; ri < 8; ri++) {
        const int r = w * 8 + ri;

        // hb for receiver r: k = tig + 4j (all lanes same addr per tig -> bcast)
        float hbreg[16];
        #pragma unroll
        for (int j = 0; j < 16; j++)
            hbreg[j] = sf[SHB + r * 64 + tig + 4 * j];

        float colacc[16];
        #pragma unroll
        for (int c = 0; c < 16; c++) colacc[c] = 0.0f;

        #pragma unroll 1
        for (int mhalf = 0; mhalf < 2; mhalf++) {
            // sender rows for this lane: m = mhalf*32 + g + mi*8
            int srow[4];
            float ewm[4];
            #pragma unroll
            for (int mi = 0; mi < 4; mi++) {
                int m = mhalf * 32 + g + mi * 8;
                int s = m + (m >= r ? 1 : 0);
                if (s > 63) s = 63;            // pad row (ew=0 kills it)
                srow[mi] = s * 68;
                ewm[mi]  = sf[SEW + r * 64 + m];
            }

            #pragma unroll 1
            for (int nhalf = 0; nhalf < 2; nhalf++) {
                float acc[2][4][4];
                #pragma unroll
                for (int mt = 0; mt < 2; mt++)
                    #pragma unroll
                    for (int nt = 0; nt < 4; nt++)
                        #pragma unroll
                        for (int q = 0; q < 4; q++) acc[mt][nt][q] = 0.0f;

                #pragma unroll
                for (int ks = 0; ks < 8; ks++) {
                    const int k0 = ks * 8 + tig;
                    const float hb0 = hbreg[2 * ks];
                    const float hb1 = hbreg[2 * ks + 1];
                    uint32_t a[2][4];
                    #pragma unroll
                    for (int mt = 0; mt < 2; mt++) {
                        float h00 = sf[SHS + srow[mt * 2]     + k0];
                        float h10 = sf[SHS + srow[mt * 2 + 1] + k0];
                        float h01 = sf[SHS + srow[mt * 2]     + k0 + 4];
                        float h11 = sf[SHS + srow[mt * 2 + 1] + k0 + 4];
                        a[mt][0] = to_tf32(relu(h00 + hb0));
                        a[mt][1] = to_tf32(relu(h10 + hb0));
                        a[mt][2] = to_tf32(relu(h01 + hb1));
                        a[mt][3] = to_tf32(relu(h11 + hb1));
                    }
                    #pragma unroll
                    for (int nt = 0; nt < 4; nt++) {
                        int frag = (nhalf * 4 + nt) * 8 + ks;
                        float2 bv = *reinterpret_cast<const float2*>(
                            &sf[SBF + frag * 64 + lane * 2]);
                        uint32_t b0 = __float_as_uint(bv.x);
                        uint32_t b1 = __float_as_uint(bv.y);
                        mma_tf32(acc[0][nt], a[0], b0, b1);
                        mma_tf32(acc[1][nt], a[1], b0, b1);
                    }
                }

                // epilogue: relu(C+bias)*ew -> column partials
                #pragma unroll
                for (int nt = 0; nt < 4; nt++) {
                    float bs0 = sf[SBIAS + nhalf * 32 + nt * 8 + 2 * tig];
                    float bs1 = sf[SBIAS + nhalf * 32 + nt * 8 + 2 * tig + 1];
                    int ci = (nhalf * 4 + nt) * 2;
                    #pragma unroll
                    for (int mt = 0; mt < 2; mt++) {
                        float ew0 = ewm[mt * 2];
                        float ew1 = ewm[mt * 2 + 1];
                        float* c4 = acc[mt][nt];
                        colacc[ci]     += relu(c4[0] + bs0) * ew0
                                        + relu(c4[2] + bs0) * ew1;
                        colacc[ci + 1] += relu(c4[1] + bs1) * ew0
                                        + relu(c4[3] + bs1) * ew1;
                    }
                }
            }
        }

        // reduce column partials across the 8 g-lanes (bits 2,3,4)
        #pragma unroll
        for (int c = 0; c < 16; c++) {
            colacc[c] += __shfl_xor_sync(FULL, colacc[c], 4);
            colacc[c] += __shfl_xor_sync(FULL, colacc[c], 8);
            colacc[c] += __shfl_xor_sync(FULL, colacc[c], 16);
        }
        // lane (g,tig) writes columns {8g+2tig, 8g+2tig+1}
        float v0 = 0.0f, v1 = 0.0f;
        #pragma unroll
        for (int nt = 0; nt < 8; nt++)
            if (g == nt) { v0 = colacc[nt * 2]; v1 = colacc[nt * 2 + 1]; }
        *reinterpret_cast<float2*>(
            &out[OUT_AUG + ((size_t)b * 64 + r) * 96 + 32 + g * 8 + 2 * tig]) =
            make_float2(v0, v1);
    }
}

// ============================================================================
// Kernel 2: node MLP head (R3 version).
// ============================================================================
struct NodeSmem {
    ull   s1I[48][64];
    ull   s2I[32][64];
    float buf[8][8][104];
    float smu[8][64];
    float sls[8][64];
    float sb1[64], sb2[64], sbm[8], sbl[8];
};

__global__ __launch_bounds__(256) void node_kernel(
    const float* __restrict__ fc1w,
    const float* __restrict__ fc1b,
    const float* __restrict__ fc2w,
    const float* __restrict__ fc2b,
    const float* __restrict__ muw,
    const float* __restrict__ mub,
    const float* __restrict__ lsw,
    const float* __restrict__ lsb,
    float* __restrict__ out)
{
    extern __shared__ char smem_raw[];
    NodeSmem* sm = reinterpret_cast<NodeSmem*>(smem_raw);

    const int tid  = threadIdx.x;
    const int lane = tid & 31;
    const int w    = tid >> 5;

    for (int i = tid; i < 48 * 64; i += 256) {
        int kp = i >> 6, c = i & 63;
        sm->s1I[kp][c] = pack2(fc1w[(2 * kp) * 64 + c], fc1w[(2 * kp + 1) * 64 + c]);
    }
    for (int i = tid; i < 32 * 64; i += 256) {
        int kp = i >> 6, c = i & 63;
        sm->s2I[kp][c] = pack2(fc2w[(2 * kp) * 64 + c], fc2w[(2 * kp + 1) * 64 + c]);
    }
    for (int i = tid; i < 64 * 8; i += 256) {
        int k = i >> 3, a = i & 7;
        sm->smu[a][k] = muw[i];
        sm->sls[a][k] = lsw[i];
    }
    if (tid < 64) { sm->sb1[tid] = fc1b[tid]; sm->sb2[tid] = fc2b[tid]; }
    if (tid < 8)  { sm->sbm[tid] = mub[tid];  sm->sbl[tid] = lsb[tid]; }
    __syncthreads();

    const int rowbase = blockIdx.x * 64 + w * 8;

    if (lane < 24) {
        #pragma unroll
        for (int rr = 0; rr < 8; rr++) {
            const float4* src = reinterpret_cast<const float4*>(
                out + OUT_AUG + (size_t)(rowbase + rr) * 96);
            *reinterpret_cast<float4*>(&sm->buf[w][rr][lane * 4]) = src[lane];
        }
    }
    __syncwarp();

    ull alo[8], ahi[8];
    #pragma unroll
    for (int rr = 0; rr < 8; rr++) { alo[rr] = 0ull; ahi[rr] = 0ull; }
    #pragma unroll 1
    for (int kp4 = 0; kp4 < 12; kp4++) {
        ull wl[4], wh[4];
        #pragma unroll
        for (int j = 0; j < 4; j++) {
            wl[j] = sm->s1I[kp4 * 4 + j][lane];
            wh[j] = sm->s1I[kp4 * 4 + j][lane + 32];
        }
        #pragma unroll
        for (int rr = 0; rr < 8; rr++) {
            const ull2* hp = reinterpret_cast<const ull2*>(&sm->buf[w][rr][kp4 * 8]);
            ull2 ha = hp[0];
            ull2 hb2 = hp[1];
            alo[rr] = fma2(ha.x,  wl[0], alo[rr]);  ahi[rr] = fma2(ha.x,  wh[0], ahi[rr]);
            alo[rr] = fma2(ha.y,  wl[1], alo[rr]);  ahi[rr] = fma2(ha.y,  wh[1], ahi[rr]);
            alo[rr] = fma2(hb2.x, wl[2], alo[rr]);  ahi[rr] = fma2(hb2.x, wh[2], ahi[rr]);
            alo[rr] = fma2(hb2.y, wl[3], alo[rr]);  ahi[rr] = fma2(hb2.y, wh[3], ahi[rr]);
        }
    }
    __syncwarp();
    {
        const float b0 = sm->sb1[lane], b1 = sm->sb1[lane + 32];
        #pragma unroll
        for (int rr = 0; rr < 8; rr++) {
            float2 pl = *reinterpret_cast<float2*>(&alo[rr]);
            float2 ph = *reinterpret_cast<float2*>(&ahi[rr]);
            sm->buf[w][rr][lane]      = relu(pl.x + pl.y + b0);
            sm->buf[w][rr][lane + 32] = relu(ph.x + ph.y + b1);
        }
    }
    __syncwarp();

    #pragma unroll
    for (int rr = 0; rr < 8; rr++) { alo[rr] = 0ull; ahi[rr] = 0ull; }
    #pragma unroll 1
    for (int kp4 = 0; kp4 < 8; kp4++) {
        ull wl[4], wh[4];
        #pragma unroll
        for (int j = 0; j < 4; j++) {
            wl[j] = sm->s2I[kp4 * 4 + j][lane];
            wh[j] = sm->s2I[kp4 * 4 + j][lane + 32];
        }
        #pragma unroll
        for (int rr = 0; rr < 8; rr++) {
            const ull2* hp = reinterpret_cast<const ull2*>(&sm->buf[w][rr][kp4 * 8]);
            ull2 ha = hp[0];
            ull2 hb2 = hp[1];
            alo[rr] = fma2(ha.x,  wl[0], alo[rr]);  ahi[rr] = fma2(ha.x,  wh[0], ahi[rr]);
            alo[rr] = fma2(ha.y,  wl[1], alo[rr]);  ahi[rr] = fma2(ha.y,  wh[1], ahi[rr]);
            alo[rr] = fma2(hb2.x, wl[2], alo[rr]);  ahi[rr] = fma2(hb2.x, wh[2], ahi[rr]);
            alo[rr] = fma2(hb2.y, wl[3], alo[rr]);  ahi[rr] = fma2(hb2.y, wh[3], ahi[rr]);
        }
    }
    __syncwarp();
    {
        const float b0 = sm->sb2[lane], b1 = sm->sb2[lane + 32];
        #pragma unroll
        for (int rr = 0; rr < 8; rr++) {
            float2 pl = *reinterpret_cast<float2*>(&alo[rr]);
            float2 ph = *reinterpret_cast<float2*>(&ahi[rr]);
            sm->buf[w][rr][lane]      = relu(pl.x + pl.y + b0);
            sm->buf[w][rr][lane + 32] = relu(ph.x + ph.y + b1);
        }
    }
    __syncwarp();

    const int a   = lane >> 2;
    const int seg = lane & 3;
    #pragma unroll 1
    for (int rr = 0; rr < 8; rr++) {
        const int row = rowbase + rr;
        const float* trow = &sm->buf[w][rr][0];
        float pm = 0.f, pl = 0.f;
        #pragma unroll
        for (int j4 = 0; j4 < 4; j4++) {
            int k = seg * 16 + j4 * 4;
            float4 tv = *reinterpret_cast<const float4*>(trow + k);
            float4 mv = *reinterpret_cast<const float4*>(&sm->smu[a][k]);
            float4 lv = *reinterpret_cast<const float4*>(&sm->sls[a][k]);
            pm = fmaf(tv.x, mv.x, pm); pm = fmaf(tv.y, mv.y, pm);
            pm = fmaf(tv.z, mv.z, pm); pm = fmaf(tv.w, mv.w, pm);
            pl = fmaf(tv.x, lv.x, pl); pl = fmaf(tv.y, lv.y, pl);
            pl = fmaf(tv.z, lv.z, pl); pl = fmaf(tv.w, lv.w, pl);
        }
        pm += __shfl_xor_sync(FULL, pm, 1); pm += __shfl_xor_sync(FULL, pm, 2);
        pl += __shfl_xor_sync(FULL, pl, 1); pl += __shfl_xor_sync(FULL, pl, 2);

        float mu = pm + sm->sbm[a];
        float ls = fminf(fmaxf(pl + sm->sbl[a], -3.0f), 1.0f);
        float x  = -2.0f * mu;
        float sp = fmaxf(x, 0.0f) + log1pf(expf(-fabsf(x)));
        float c  = -ls - HALF_LOG_2PI_F - 2.0f * (LOG2_F - mu - sp);

        if (seg == 0) out[OUT_TANH + (size_t)row * Aa + a] = tanhf(mu);

        float val = (seg == 0) ? c : 0.f;
        val += __shfl_xor_sync(FULL, val, 4);
        val += __shfl_xor_sync(FULL, val, 8);
        val += __shfl_xor_sync(FULL, val, 16);
        if (lane == 0) out[OUT_LOGP + row] = val;
    }
}

extern "C" void kernel_launch(void* const* d_in, const int* in_sizes, int n_in,
                              void* d_out, int out_size) {
    (void)in_sizes; (void)n_in; (void)out_size;
    const float* inputs = (const float*)d_in[0];
    const float* edges  = (const float*)d_in[1];
    const float* m1w    = (const float*)d_in[2];
    const float* m1b    = (const float*)d_in[3];
    const float* m2w    = (const float*)d_in[4];
    const float* m2b    = (const float*)d_in[5];
    const float* fc1w   = (const float*)d_in[6];
    const float* fc1b   = (const float*)d_in[7];
    const float* fc2w   = (const float*)d_in[8];
    const float* fc2b   = (const float*)d_in[9];
    const float* muw    = (const float*)d_in[10];
    const float* mub    = (const float*)d_in[11];
    const float* lsw    = (const float*)d_in[12];
    const float* lsb    = (const float*)d_in[13];
    float* out = (float*)d_out;

    cudaFuncSetAttribute(edge_kernel,
                         cudaFuncAttributeMaxDynamicSharedMemorySize, EDGE_SMEM_B);
    cudaFuncSetAttribute(node_kernel,
                         cudaFuncAttributeMaxDynamicSharedMemorySize,
                         (int)sizeof(NodeSmem));

    mlp1_kernel<<<4096, 256>>>(inputs, m1w, m1b, out);
    edge_kernel<<<512, 256, EDGE_SMEM_B>>>(edges, m2w, m2b, out);
    node_kernel<<<512, 256, sizeof(NodeSmem)>>>(
        fc1w, fc1b, fc2w, fc2b, muw, mub, lsw, lsb, out);
}